// round 2
// baseline (speedup 1.0000x reference)
#include <cuda_runtime.h>

// GazeLSTM: N=8192 rows, L=32 steps, H=256, 4H=1024, IN=2, OUT=128.
// Persistent-state kernel, 128 CTAs x 256 threads, 64 rows/CTA.
// Inner product uses packed fma.rn.f32x2 (FFMA2) pairing consecutive k.

#define Hh      256
#define FOURH   1024
#define LSTEPS  32
#define NB      64
#define NCTA    128
#define PADK    258       // even pitch -> 8B-aligned (k,k+1) pairs
#define KT      64        // k's per staged panel
#define OUTD    128
#define NPANEL  36        // 32 gate panels (8 m x 4 kt) + 4 FC panels

// ---- prologue-built weights (module-scope device arrays; no runtime alloc) ----
// pair layout: g_Wt2[(k2*1024 + col)*2 + p] = W_hh[(q*256+j)][2*k2+p], col=j*4+q
__device__ float g_Wt2[Hh * FOURH];
__device__ float g_bias[FOURH];            // bias[j*4+q] = b_ih[g]+b_hh[g]
__device__ float g_Wihp[FOURH * 2];        // Wihp[j*4+q][s] = W_ih[g][s]
__device__ float g_fcT2[Hh * OUTD];        // g_fcT2[(k2*128+o)*2+p] = fc_w[o][2*k2+p]

__global__ void prep_kernel(const float* __restrict__ W_ih,
                            const float* __restrict__ W_hh,
                            const float* __restrict__ b_ih,
                            const float* __restrict__ b_hh,
                            const float* __restrict__ fc_w) {
    int idx = blockIdx.x * blockDim.x + threadIdx.x;
    int stride = gridDim.x * blockDim.x;
    for (int f = idx; f < Hh * FOURH; f += stride) {
        int k2 = f >> 11, rem = f & 2047;
        int col = rem >> 1, p = rem & 1;
        int j = col >> 2, q = col & 3;
        g_Wt2[f] = W_hh[(q * Hh + j) * Hh + (2 * k2 + p)];
    }
    for (int f = idx; f < Hh * OUTD; f += stride) {
        int k2 = f >> 8, rem = f & 255;
        int o = rem >> 1, p = rem & 1;
        g_fcT2[f] = fc_w[o * Hh + (2 * k2 + p)];
    }
    if (idx < FOURH) {
        int j = idx >> 2, q = idx & 3;
        int g = q * Hh + j;
        g_bias[idx]         = b_ih[g] + b_hh[g];
        g_Wihp[idx * 2 + 0] = W_ih[g * 2 + 0];
        g_Wihp[idx * 2 + 1] = W_ih[g * 2 + 1];
    }
}

__device__ __forceinline__ void fma2(unsigned long long& d,
                                     unsigned long long a,
                                     unsigned long long b) {
    asm("fma.rn.f32x2 %0, %1, %2, %0;" : "+l"(d) : "l"(a), "l"(b));
}
__device__ __forceinline__ unsigned long long pack2(float lo, float hi) {
    unsigned long long r;
    asm("mov.b64 %0, {%1, %2};" : "=l"(r) : "f"(lo), "f"(hi));
    return r;
}
__device__ __forceinline__ float fold2(unsigned long long v) {
    float lo, hi;
    asm("mov.b64 {%0, %1}, %2;" : "=f"(lo), "=f"(hi) : "l"(v));
    return lo + hi;
}
__device__ __forceinline__ float sigf(float v) {
    return __fdividef(1.0f, 1.0f + __expf(-v));
}
__device__ __forceinline__ float tanhfast(float v) {
    float e = __expf(-2.0f * v);
    return __fdividef(1.0f - e, 1.0f + e);
}

// panel source address (float4 granularity), p in [0, NPANEL)
__device__ __forceinline__ const float4* panel_src(int p, int e4) {
    if (p < 32) {
        int m = p >> 2, kt = p & 3;
        int k2g = kt * 32 + (e4 >> 6);
        return reinterpret_cast<const float4*>(
            g_Wt2 + (size_t)k2g * 2048 + m * 256 + (e4 & 63) * 4);
    } else {
        int kt = p - 32;
        int k2g = kt * 32 + (e4 >> 6);
        return reinterpret_cast<const float4*>(
            g_fcT2 + (size_t)k2g * 256 + (e4 & 63) * 4);
    }
}

// smem floats: H dbl buf 2*64*258=33024, panel 8192, C 16384  -> 230,400 B
#define SMEM_FLOATS (2 * NB * PADK + (KT / 2) * 256 + NB * Hh)

__global__ __launch_bounds__(256, 1)
void lstm_kernel(const float* __restrict__ x,     // [8192][32][2]
                 const float* __restrict__ fc_b,  // [128]
                 float* __restrict__ out) {       // [8192][32][128]
    extern __shared__ float sm[];
    float* Hbuf0 = sm;                       // [64][258]
    float* Hbuf1 = sm + NB * PADK;
    float* Wp    = sm + 2 * NB * PADK;       // [32 k2][256] pair-interleaved
    float* Cs    = Wp + (KT / 2) * 256;      // [64][256]

    const int tx = threadIdx.x;
    const int ty = tx >> 5;        // warp id: row group
    const int tj = tx & 31;
    const int rowbase = ty * 8;
    const int r0 = blockIdx.x * NB;

    for (int i = tx; i < NB * PADK; i += 256) Hbuf0[i] = 0.0f;
    for (int i = tx; i < NB * Hh;  i += 256) Cs[i] = 0.0f;

    // prestage panel 0 (gates m=0, kt=0)
    {
        float4 pf[8];
#pragma unroll
        for (int i = 0; i < 8; ++i) pf[i] = __ldg(panel_src(0, tx + i * 256));
        __syncthreads();
#pragma unroll
        for (int i = 0; i < 8; ++i)
            reinterpret_cast<float4*>(Wp)[tx + i * 256] = pf[i];
        __syncthreads();
    }

    const float4 fb = *reinterpret_cast<const float4*>(fc_b + tj * 4);
    int pcur = 0;

#pragma unroll 1
    for (int l = 0; l < LSTEPS; ++l) {
        float* cur = (l & 1) ? Hbuf1 : Hbuf0;
        float* nxt = (l & 1) ? Hbuf0 : Hbuf1;

        float x0[8], x1[8];
#pragma unroll
        for (int ri = 0; ri < 8; ++ri) {
            const float* xp = x + (size_t)(r0 + rowbase + ri) * (LSTEPS * 2) + l * 2;
            x0[ri] = __ldg(xp);
            x1[ri] = __ldg(xp + 1);
        }

        // ---- gates: 8 chunks of 128 permuted cols ----
#pragma unroll 1
        for (int m = 0; m < 8; ++m) {
            const int j = m * 32 + tj;
            const float4 wA = *reinterpret_cast<const float4*>(g_Wihp + j * 8);
            const float4 wB = *reinterpret_cast<const float4*>(g_Wihp + j * 8 + 4);
            const float4 bs = *reinterpret_cast<const float4*>(g_bias + j * 4);

            unsigned long long acc[8][4];
#pragma unroll
            for (int ri = 0; ri < 8; ++ri) {
                acc[ri][0] = pack2(bs.x + x0[ri] * wA.x + x1[ri] * wA.y, 0.0f);
                acc[ri][1] = pack2(bs.y + x0[ri] * wA.z + x1[ri] * wA.w, 0.0f);
                acc[ri][2] = pack2(bs.z + x0[ri] * wB.x + x1[ri] * wB.y, 0.0f);
                acc[ri][3] = pack2(bs.w + x0[ri] * wB.z + x1[ri] * wB.w, 0.0f);
            }

#pragma unroll 1
            for (int kt = 0; kt < 4; ++kt) {
                // register-prefetch next panel while computing this one
                const int pn = (pcur + 1 == NPANEL) ? 0 : pcur + 1;
                float4 pf[8];
#pragma unroll
                for (int i = 0; i < 8; ++i)
                    pf[i] = __ldg(panel_src(pn, tx + i * 256));

                const float* arow = cur + kt * KT;  // + row*PADK
#pragma unroll 8
                for (int kk2 = 0; kk2 < KT / 2; ++kk2) {
                    const ulonglong2 B0 = *reinterpret_cast<const ulonglong2*>(
                        Wp + kk2 * 256 + tj * 8);
                    const ulonglong2 B1 = *reinterpret_cast<const ulonglong2*>(
                        Wp + kk2 * 256 + tj * 8 + 4);
#pragma unroll
                    for (int ri = 0; ri < 8; ++ri) {
                        const unsigned long long a2 =
                            *reinterpret_cast<const unsigned long long*>(
                                arow + (rowbase + ri) * PADK + kk2 * 2);
                        fma2(acc[ri][0], a2, B0.x);
                        fma2(acc[ri][1], a2, B0.y);
                        fma2(acc[ri][2], a2, B1.x);
                        fma2(acc[ri][3], a2, B1.y);
                    }
                }
                __syncthreads();
#pragma unroll
                for (int i = 0; i < 8; ++i)
                    reinterpret_cast<float4*>(Wp)[tx + i * 256] = pf[i];
                __syncthreads();
                pcur = pn;
            }

            // nonlinearity + state (gate order i,f,g,o). H/C are warp-private.
#pragma unroll
            for (int ri = 0; ri < 8; ++ri) {
                const int cidx = (rowbase + ri) * Hh + j;
                const float ig = sigf(fold2(acc[ri][0]));
                const float fg = sigf(fold2(acc[ri][1]));
                const float gg = tanhfast(fold2(acc[ri][2]));
                const float og = sigf(fold2(acc[ri][3]));
                const float cn = fg * Cs[cidx] + ig * gg;
                Cs[cidx] = cn;
                nxt[(rowbase + ri) * PADK + j] = og * tanhfast(cn);
            }
            __syncwarp();
        }

        // ---- FC: 128 outputs, o = tj*4+q ----
        unsigned long long facc[8][4];
#pragma unroll
        for (int ri = 0; ri < 8; ++ri) {
            facc[ri][0] = pack2(fb.x, 0.0f);
            facc[ri][1] = pack2(fb.y, 0.0f);
            facc[ri][2] = pack2(fb.z, 0.0f);
            facc[ri][3] = pack2(fb.w, 0.0f);
        }
#pragma unroll 1
        for (int kt = 0; kt < 4; ++kt) {
            const int pn = (pcur + 1 == NPANEL) ? 0 : pcur + 1;
            float4 pf[8];
#pragma unroll
            for (int i = 0; i < 8; ++i)
                pf[i] = __ldg(panel_src(pn, tx + i * 256));

            const float* arow = nxt + kt * KT;
#pragma unroll 8
            for (int kk2 = 0; kk2 < KT / 2; ++kk2) {
                const ulonglong2 B0 = *reinterpret_cast<const ulonglong2*>(
                    Wp + kk2 * 256 + tj * 8);
                const ulonglong2 B1 = *reinterpret_cast<const ulonglong2*>(
                    Wp + kk2 * 256 + tj * 8 + 4);
#pragma unroll
                for (int ri = 0; ri < 8; ++ri) {
                    const unsigned long long a2 =
                        *reinterpret_cast<const unsigned long long*>(
                            arow + (rowbase + ri) * PADK + kk2 * 2);
                    fma2(facc[ri][0], a2, B0.x);
                    fma2(facc[ri][1], a2, B0.y);
                    fma2(facc[ri][2], a2, B1.x);
                    fma2(facc[ri][3], a2, B1.y);
                }
            }
            __syncthreads();
#pragma unroll
            for (int i = 0; i < 8; ++i)
                reinterpret_cast<float4*>(Wp)[tx + i * 256] = pf[i];
            __syncthreads();
            pcur = pn;
        }

#pragma unroll
        for (int ri = 0; ri < 8; ++ri) {
            const int n = r0 + rowbase + ri;
            float4 v;
            v.x = fold2(facc[ri][0]);
            v.y = fold2(facc[ri][1]);
            v.z = fold2(facc[ri][2]);
            v.w = fold2(facc[ri][3]);
            *reinterpret_cast<float4*>(
                out + (size_t)n * (LSTEPS * OUTD) + l * OUTD + tj * 4) = v;
        }
    }
}

extern "C" void kernel_launch(void* const* d_in, const int* in_sizes, int n_in,
                              void* d_out, int out_size) {
    const float* x    = (const float*)d_in[0];
    const float* W_ih = (const float*)d_in[1];
    const float* W_hh = (const float*)d_in[2];
    const float* b_ih = (const float*)d_in[3];
    const float* b_hh = (const float*)d_in[4];
    const float* fc_w = (const float*)d_in[5];
    const float* fc_b = (const float*)d_in[6];
    float* out = (float*)d_out;

    prep_kernel<<<128, 256>>>(W_ih, W_hh, b_ih, b_hh, fc_w);

    const size_t smem_bytes = (size_t)SMEM_FLOATS * sizeof(float);  // 230,400 B
    cudaFuncSetAttribute(lstm_kernel, cudaFuncAttributeMaxDynamicSharedMemorySize,
                         (int)smem_bytes);
    lstm_kernel<<<NCTA, 256, smem_bytes>>>(x, fc_b, out);
}

// round 3
// speedup vs baseline: 1.0030x; 1.0030x over previous
#include <cuda_runtime.h>

// GazeLSTM: N=8192 rows, L=32 steps, H=256, 4H=1024, IN=2, OUT=128.
// Persistent-state kernel, 128 CTAs x 256 threads, 64 rows/CTA.
// Inner product uses packed fma.rn.f32x2 (FFMA2) pairing consecutive k.

#define Hh      256
#define FOURH   1024
#define LSTEPS  32
#define NB      64
#define NCTA    128
#define PADK    258       // even pitch -> 8B-aligned (k,k+1) pairs
#define KT      64        // k's per staged panel
#define OUTD    128
#define NPANEL  36        // 32 gate panels (8 m x 4 kt) + 4 FC panels

// ---- prologue-built weights (module-scope device arrays; no runtime alloc) ----
// pair layout: g_Wt2[(k2*1024 + col)*2 + p] = W_hh[(q*256+j)][2*k2+p], col=j*4+q
__device__ float g_Wt2[Hh * FOURH];
__device__ float g_bias[FOURH];            // bias[j*4+q] = b_ih[g]+b_hh[g]
__device__ float g_Wihp[FOURH * 2];        // Wihp[j*4+q][s] = W_ih[g][s]
__device__ float g_fcT2[Hh * OUTD];        // g_fcT2[(k2*128+o)*2+p] = fc_w[o][2*k2+p]

__global__ void prep_kernel(const float* __restrict__ W_ih,
                            const float* __restrict__ W_hh,
                            const float* __restrict__ b_ih,
                            const float* __restrict__ b_hh,
                            const float* __restrict__ fc_w) {
    int idx = blockIdx.x * blockDim.x + threadIdx.x;
    int stride = gridDim.x * blockDim.x;
    for (int f = idx; f < Hh * FOURH; f += stride) {
        int k2 = f >> 11, rem = f & 2047;
        int col = rem >> 1, p = rem & 1;
        int j = col >> 2, q = col & 3;
        g_Wt2[f] = W_hh[(q * Hh + j) * Hh + (2 * k2 + p)];
    }
    for (int f = idx; f < Hh * OUTD; f += stride) {
        int k2 = f >> 8, rem = f & 255;
        int o = rem >> 1, p = rem & 1;
        g_fcT2[f] = fc_w[o * Hh + (2 * k2 + p)];
    }
    if (idx < FOURH) {
        int j = idx >> 2, q = idx & 3;
        int g = q * Hh + j;
        g_bias[idx]         = b_ih[g] + b_hh[g];
        g_Wihp[idx * 2 + 0] = W_ih[g * 2 + 0];
        g_Wihp[idx * 2 + 1] = W_ih[g * 2 + 1];
    }
}

__device__ __forceinline__ void fma2(unsigned long long& d,
                                     unsigned long long a,
                                     unsigned long long b) {
    asm("fma.rn.f32x2 %0, %1, %2, %0;" : "+l"(d) : "l"(a), "l"(b));
}
__device__ __forceinline__ unsigned long long pack2(float lo, float hi) {
    unsigned long long r;
    asm("mov.b64 %0, {%1, %2};" : "=l"(r) : "f"(lo), "f"(hi));
    return r;
}
__device__ __forceinline__ float fold2(unsigned long long v) {
    float lo, hi;
    asm("mov.b64 {%0, %1}, %2;" : "=f"(lo), "=f"(hi) : "l"(v));
    return lo + hi;
}
__device__ __forceinline__ float sigf(float v) {
    return __fdividef(1.0f, 1.0f + __expf(-v));
}
__device__ __forceinline__ float tanhfast(float v) {
    float e = __expf(-2.0f * v);
    return __fdividef(1.0f - e, 1.0f + e);
}

// panel source address (float4 granularity), p in [0, NPANEL)
__device__ __forceinline__ const float4* panel_src(int p, int e4) {
    if (p < 32) {
        int m = p >> 2, kt = p & 3;
        int k2g = kt * 32 + (e4 >> 6);
        return reinterpret_cast<const float4*>(
            g_Wt2 + (size_t)k2g * 2048 + m * 256 + (e4 & 63) * 4);
    } else {
        int kt = p - 32;
        int k2g = kt * 32 + (e4 >> 6);
        return reinterpret_cast<const float4*>(
            g_fcT2 + (size_t)k2g * 256 + (e4 & 63) * 4);
    }
}

// smem floats: H dbl buf 2*64*258=33024, panel 8192, C 16384  -> 230,400 B
#define SMEM_FLOATS (2 * NB * PADK + (KT / 2) * 256 + NB * Hh)

__global__ __launch_bounds__(256, 1)
void lstm_kernel(const float* __restrict__ x,     // [8192][32][2]
                 const float* __restrict__ fc_b,  // [128]
                 float* __restrict__ out) {       // [8192][32][128]
    extern __shared__ float sm[];
    float* Hbuf0 = sm;                       // [64][258]
    float* Hbuf1 = sm + NB * PADK;
    float* Wp    = sm + 2 * NB * PADK;       // [32 k2][256] pair-interleaved
    float* Cs    = Wp + (KT / 2) * 256;      // [64][256]

    const int tx = threadIdx.x;
    const int ty = tx >> 5;        // warp id: row group
    const int tj = tx & 31;
    const int rowbase = ty * 8;
    const int r0 = blockIdx.x * NB;

    for (int i = tx; i < NB * PADK; i += 256) Hbuf0[i] = 0.0f;
    for (int i = tx; i < NB * Hh;  i += 256) Cs[i] = 0.0f;

    // prestage panel 0 (gates m=0, kt=0)
    {
        float4 pf[8];
#pragma unroll
        for (int i = 0; i < 8; ++i) pf[i] = __ldg(panel_src(0, tx + i * 256));
        __syncthreads();
#pragma unroll
        for (int i = 0; i < 8; ++i)
            reinterpret_cast<float4*>(Wp)[tx + i * 256] = pf[i];
        __syncthreads();
    }

    const float4 fb = *reinterpret_cast<const float4*>(fc_b + tj * 4);
    int pcur = 0;

#pragma unroll 1
    for (int l = 0; l < LSTEPS; ++l) {
        float* cur = (l & 1) ? Hbuf1 : Hbuf0;
        float* nxt = (l & 1) ? Hbuf0 : Hbuf1;

        float x0[8], x1[8];
#pragma unroll
        for (int ri = 0; ri < 8; ++ri) {
            const float* xp = x + (size_t)(r0 + rowbase + ri) * (LSTEPS * 2) + l * 2;
            x0[ri] = __ldg(xp);
            x1[ri] = __ldg(xp + 1);
        }

        // ---- gates: 8 chunks of 128 permuted cols ----
#pragma unroll 1
        for (int m = 0; m < 8; ++m) {
            const int j = m * 32 + tj;
            const float4 wA = *reinterpret_cast<const float4*>(g_Wihp + j * 8);
            const float4 wB = *reinterpret_cast<const float4*>(g_Wihp + j * 8 + 4);
            const float4 bs = *reinterpret_cast<const float4*>(g_bias + j * 4);

            unsigned long long acc[8][4];
#pragma unroll
            for (int ri = 0; ri < 8; ++ri) {
                acc[ri][0] = pack2(bs.x + x0[ri] * wA.x + x1[ri] * wA.y, 0.0f);
                acc[ri][1] = pack2(bs.y + x0[ri] * wA.z + x1[ri] * wA.w, 0.0f);
                acc[ri][2] = pack2(bs.z + x0[ri] * wB.x + x1[ri] * wB.y, 0.0f);
                acc[ri][3] = pack2(bs.w + x0[ri] * wB.z + x1[ri] * wB.w, 0.0f);
            }

#pragma unroll 1
            for (int kt = 0; kt < 4; ++kt) {
                // register-prefetch next panel while computing this one
                const int pn = (pcur + 1 == NPANEL) ? 0 : pcur + 1;
                float4 pf[8];
#pragma unroll
                for (int i = 0; i < 8; ++i)
                    pf[i] = __ldg(panel_src(pn, tx + i * 256));

                const float* arow = cur + kt * KT;  // + row*PADK
#pragma unroll 8
                for (int kk2 = 0; kk2 < KT / 2; ++kk2) {
                    const ulonglong2 B0 = *reinterpret_cast<const ulonglong2*>(
                        Wp + kk2 * 256 + tj * 8);
                    const ulonglong2 B1 = *reinterpret_cast<const ulonglong2*>(
                        Wp + kk2 * 256 + tj * 8 + 4);
#pragma unroll
                    for (int ri = 0; ri < 8; ++ri) {
                        const unsigned long long a2 =
                            *reinterpret_cast<const unsigned long long*>(
                                arow + (rowbase + ri) * PADK + kk2 * 2);
                        fma2(acc[ri][0], a2, B0.x);
                        fma2(acc[ri][1], a2, B0.y);
                        fma2(acc[ri][2], a2, B1.x);
                        fma2(acc[ri][3], a2, B1.y);
                    }
                }
                __syncthreads();
#pragma unroll
                for (int i = 0; i < 8; ++i)
                    reinterpret_cast<float4*>(Wp)[tx + i * 256] = pf[i];
                __syncthreads();
                pcur = pn;
            }

            // nonlinearity + state (gate order i,f,g,o). H/C are warp-private.
#pragma unroll
            for (int ri = 0; ri < 8; ++ri) {
                const int cidx = (rowbase + ri) * Hh + j;
                const float ig = sigf(fold2(acc[ri][0]));
                const float fg = sigf(fold2(acc[ri][1]));
                const float gg = tanhfast(fold2(acc[ri][2]));
                const float og = sigf(fold2(acc[ri][3]));
                const float cn = fg * Cs[cidx] + ig * gg;
                Cs[cidx] = cn;
                nxt[(rowbase + ri) * PADK + j] = og * tanhfast(cn);
            }
            __syncwarp();
        }

        // ---- FC: 128 outputs, o = tj*4+q ----
        unsigned long long facc[8][4];
#pragma unroll
        for (int ri = 0; ri < 8; ++ri) {
            facc[ri][0] = pack2(fb.x, 0.0f);
            facc[ri][1] = pack2(fb.y, 0.0f);
            facc[ri][2] = pack2(fb.z, 0.0f);
            facc[ri][3] = pack2(fb.w, 0.0f);
        }
#pragma unroll 1
        for (int kt = 0; kt < 4; ++kt) {
            const int pn = (pcur + 1 == NPANEL) ? 0 : pcur + 1;
            float4 pf[8];
#pragma unroll
            for (int i = 0; i < 8; ++i)
                pf[i] = __ldg(panel_src(pn, tx + i * 256));

            const float* arow = nxt + kt * KT;
#pragma unroll 8
            for (int kk2 = 0; kk2 < KT / 2; ++kk2) {
                const ulonglong2 B0 = *reinterpret_cast<const ulonglong2*>(
                    Wp + kk2 * 256 + tj * 8);
                const ulonglong2 B1 = *reinterpret_cast<const ulonglong2*>(
                    Wp + kk2 * 256 + tj * 8 + 4);
#pragma unroll
                for (int ri = 0; ri < 8; ++ri) {
                    const unsigned long long a2 =
                        *reinterpret_cast<const unsigned long long*>(
                            arow + (rowbase + ri) * PADK + kk2 * 2);
                    fma2(facc[ri][0], a2, B0.x);
                    fma2(facc[ri][1], a2, B0.y);
                    fma2(facc[ri][2], a2, B1.x);
                    fma2(facc[ri][3], a2, B1.y);
                }
            }
            __syncthreads();
#pragma unroll
            for (int i = 0; i < 8; ++i)
                reinterpret_cast<float4*>(Wp)[tx + i * 256] = pf[i];
            __syncthreads();
            pcur = pn;
        }

#pragma unroll
        for (int ri = 0; ri < 8; ++ri) {
            const int n = r0 + rowbase + ri;
            float4 v;
            v.x = fold2(facc[ri][0]);
            v.y = fold2(facc[ri][1]);
            v.z = fold2(facc[ri][2]);
            v.w = fold2(facc[ri][3]);
            *reinterpret_cast<float4*>(
                out + (size_t)n * (LSTEPS * OUTD) + l * OUTD + tj * 4) = v;
        }
    }
}

extern "C" void kernel_launch(void* const* d_in, const int* in_sizes, int n_in,
                              void* d_out, int out_size) {
    const float* x    = (const float*)d_in[0];
    const float* W_ih = (const float*)d_in[1];
    const float* W_hh = (const float*)d_in[2];
    const float* b_ih = (const float*)d_in[3];
    const float* b_hh = (const float*)d_in[4];
    const float* fc_w = (const float*)d_in[5];
    const float* fc_b = (const float*)d_in[6];
    float* out = (float*)d_out;

    prep_kernel<<<128, 256>>>(W_ih, W_hh, b_ih, b_hh, fc_w);

    const size_t smem_bytes = (size_t)SMEM_FLOATS * sizeof(float);  // 230,400 B
    cudaFuncSetAttribute(lstm_kernel, cudaFuncAttributeMaxDynamicSharedMemorySize,
                         (int)smem_bytes);
    lstm_kernel<<<NCTA, 256, smem_bytes>>>(x, fc_b, out);
}

// round 4
// speedup vs baseline: 1.0033x; 1.0003x over previous
#include <cuda_runtime.h>

// GazeLSTM: N=8192 rows, L=32 steps, H=256, 4H=1024, IN=2, OUT=128.
// Persistent-state kernel, 128 CTAs x 256 threads, 64 rows/CTA.
// Inner product uses packed fma.rn.f32x2 (FFMA2) pairing consecutive k.

#define Hh      256
#define FOURH   1024
#define LSTEPS  32
#define NB      64
#define NCTA    128
#define PADK    258       // even pitch -> 8B-aligned (k,k+1) pairs
#define KT      64        // k's per staged panel
#define OUTD    128
#define NPANEL  36        // 32 gate panels (8 m x 4 kt) + 4 FC panels

// ---- prologue-built weights (module-scope device arrays; no runtime alloc) ----
// pair layout: g_Wt2[(k2*1024 + col)*2 + p] = W_hh[(q*256+j)][2*k2+p], col=j*4+q
__device__ float g_Wt2[Hh * FOURH];
__device__ float g_bias[FOURH];            // bias[j*4+q] = b_ih[g]+b_hh[g]
__device__ float g_Wihp[FOURH * 2];        // Wihp[j*4+q][s] = W_ih[g][s]
__device__ float g_fcT2[Hh * OUTD];        // g_fcT2[(k2*128+o)*2+p] = fc_w[o][2*k2+p]

__global__ void prep_kernel(const float* __restrict__ W_ih,
                            const float* __restrict__ W_hh,
                            const float* __restrict__ b_ih,
                            const float* __restrict__ b_hh,
                            const float* __restrict__ fc_w) {
    int idx = blockIdx.x * blockDim.x + threadIdx.x;
    int stride = gridDim.x * blockDim.x;
    for (int f = idx; f < Hh * FOURH; f += stride) {
        int k2 = f >> 11, rem = f & 2047;
        int col = rem >> 1, p = rem & 1;
        int j = col >> 2, q = col & 3;
        g_Wt2[f] = W_hh[(q * Hh + j) * Hh + (2 * k2 + p)];
    }
    for (int f = idx; f < Hh * OUTD; f += stride) {
        int k2 = f >> 8, rem = f & 255;
        int o = rem >> 1, p = rem & 1;
        g_fcT2[f] = fc_w[o * Hh + (2 * k2 + p)];
    }
    if (idx < FOURH) {
        int j = idx >> 2, q = idx & 3;
        int g = q * Hh + j;
        g_bias[idx]         = b_ih[g] + b_hh[g];
        g_Wihp[idx * 2 + 0] = W_ih[g * 2 + 0];
        g_Wihp[idx * 2 + 1] = W_ih[g * 2 + 1];
    }
}

__device__ __forceinline__ void fma2(unsigned long long& d,
                                     unsigned long long a,
                                     unsigned long long b) {
    asm("fma.rn.f32x2 %0, %1, %2, %0;" : "+l"(d) : "l"(a), "l"(b));
}
__device__ __forceinline__ unsigned long long pack2(float lo, float hi) {
    unsigned long long r;
    asm("mov.b64 %0, {%1, %2};" : "=l"(r) : "f"(lo), "f"(hi));
    return r;
}
__device__ __forceinline__ float fold2(unsigned long long v) {
    float lo, hi;
    asm("mov.b64 {%0, %1}, %2;" : "=f"(lo), "=f"(hi) : "l"(v));
    return lo + hi;
}
__device__ __forceinline__ float sigf(float v) {
    return __fdividef(1.0f, 1.0f + __expf(-v));
}
__device__ __forceinline__ float tanhfast(float v) {
    float e = __expf(-2.0f * v);
    return __fdividef(1.0f - e, 1.0f + e);
}

// panel source address (float4 granularity), p in [0, NPANEL)
__device__ __forceinline__ const float4* panel_src(int p, int e4) {
    if (p < 32) {
        int m = p >> 2, kt = p & 3;
        int k2g = kt * 32 + (e4 >> 6);
        return reinterpret_cast<const float4*>(
            g_Wt2 + (size_t)k2g * 2048 + m * 256 + (e4 & 63) * 4);
    } else {
        int kt = p - 32;
        int k2g = kt * 32 + (e4 >> 6);
        return reinterpret_cast<const float4*>(
            g_fcT2 + (size_t)k2g * 256 + (e4 & 63) * 4);
    }
}

// smem floats: H dbl buf 2*64*258=33024, panel 8192, C 16384  -> 230,400 B
#define SMEM_FLOATS (2 * NB * PADK + (KT / 2) * 256 + NB * Hh)

__global__ __launch_bounds__(256, 1)
void lstm_kernel(const float* __restrict__ x,     // [8192][32][2]
                 const float* __restrict__ fc_b,  // [128]
                 float* __restrict__ out) {       // [8192][32][128]
    extern __shared__ float sm[];
    float* Hbuf0 = sm;                       // [64][258]
    float* Hbuf1 = sm + NB * PADK;
    float* Wp    = sm + 2 * NB * PADK;       // [32 k2][256] pair-interleaved
    float* Cs    = Wp + (KT / 2) * 256;      // [64][256]

    const int tx = threadIdx.x;
    const int ty = tx >> 5;        // warp id: row group
    const int tj = tx & 31;
    const int rowbase = ty * 8;
    const int r0 = blockIdx.x * NB;

    for (int i = tx; i < NB * PADK; i += 256) Hbuf0[i] = 0.0f;
    for (int i = tx; i < NB * Hh;  i += 256) Cs[i] = 0.0f;

    // prestage panel 0 (gates m=0, kt=0)
    {
        float4 pf[8];
#pragma unroll
        for (int i = 0; i < 8; ++i) pf[i] = __ldg(panel_src(0, tx + i * 256));
        __syncthreads();
#pragma unroll
        for (int i = 0; i < 8; ++i)
            reinterpret_cast<float4*>(Wp)[tx + i * 256] = pf[i];
        __syncthreads();
    }

    const float4 fb = *reinterpret_cast<const float4*>(fc_b + tj * 4);
    int pcur = 0;

#pragma unroll 1
    for (int l = 0; l < LSTEPS; ++l) {
        float* cur = (l & 1) ? Hbuf1 : Hbuf0;
        float* nxt = (l & 1) ? Hbuf0 : Hbuf1;

        float x0[8], x1[8];
#pragma unroll
        for (int ri = 0; ri < 8; ++ri) {
            const float* xp = x + (size_t)(r0 + rowbase + ri) * (LSTEPS * 2) + l * 2;
            x0[ri] = __ldg(xp);
            x1[ri] = __ldg(xp + 1);
        }

        // ---- gates: 8 chunks of 128 permuted cols ----
#pragma unroll 1
        for (int m = 0; m < 8; ++m) {
            const int j = m * 32 + tj;
            const float4 wA = *reinterpret_cast<const float4*>(g_Wihp + j * 8);
            const float4 wB = *reinterpret_cast<const float4*>(g_Wihp + j * 8 + 4);
            const float4 bs = *reinterpret_cast<const float4*>(g_bias + j * 4);

            unsigned long long acc[8][4];
#pragma unroll
            for (int ri = 0; ri < 8; ++ri) {
                acc[ri][0] = pack2(bs.x + x0[ri] * wA.x + x1[ri] * wA.y, 0.0f);
                acc[ri][1] = pack2(bs.y + x0[ri] * wA.z + x1[ri] * wA.w, 0.0f);
                acc[ri][2] = pack2(bs.z + x0[ri] * wB.x + x1[ri] * wB.y, 0.0f);
                acc[ri][3] = pack2(bs.w + x0[ri] * wB.z + x1[ri] * wB.w, 0.0f);
            }

#pragma unroll 1
            for (int kt = 0; kt < 4; ++kt) {
                // register-prefetch next panel while computing this one
                const int pn = (pcur + 1 == NPANEL) ? 0 : pcur + 1;
                float4 pf[8];
#pragma unroll
                for (int i = 0; i < 8; ++i)
                    pf[i] = __ldg(panel_src(pn, tx + i * 256));

                const float* arow = cur + kt * KT;  // + row*PADK
#pragma unroll 8
                for (int kk2 = 0; kk2 < KT / 2; ++kk2) {
                    const ulonglong2 B0 = *reinterpret_cast<const ulonglong2*>(
                        Wp + kk2 * 256 + tj * 8);
                    const ulonglong2 B1 = *reinterpret_cast<const ulonglong2*>(
                        Wp + kk2 * 256 + tj * 8 + 4);
#pragma unroll
                    for (int ri = 0; ri < 8; ++ri) {
                        const unsigned long long a2 =
                            *reinterpret_cast<const unsigned long long*>(
                                arow + (rowbase + ri) * PADK + kk2 * 2);
                        fma2(acc[ri][0], a2, B0.x);
                        fma2(acc[ri][1], a2, B0.y);
                        fma2(acc[ri][2], a2, B1.x);
                        fma2(acc[ri][3], a2, B1.y);
                    }
                }
                __syncthreads();
#pragma unroll
                for (int i = 0; i < 8; ++i)
                    reinterpret_cast<float4*>(Wp)[tx + i * 256] = pf[i];
                __syncthreads();
                pcur = pn;
            }

            // nonlinearity + state (gate order i,f,g,o). H/C are warp-private.
#pragma unroll
            for (int ri = 0; ri < 8; ++ri) {
                const int cidx = (rowbase + ri) * Hh + j;
                const float ig = sigf(fold2(acc[ri][0]));
                const float fg = sigf(fold2(acc[ri][1]));
                const float gg = tanhfast(fold2(acc[ri][2]));
                const float og = sigf(fold2(acc[ri][3]));
                const float cn = fg * Cs[cidx] + ig * gg;
                Cs[cidx] = cn;
                nxt[(rowbase + ri) * PADK + j] = og * tanhfast(cn);
            }
            __syncwarp();
        }

        // ---- FC: 128 outputs, o = tj*4+q ----
        unsigned long long facc[8][4];
#pragma unroll
        for (int ri = 0; ri < 8; ++ri) {
            facc[ri][0] = pack2(fb.x, 0.0f);
            facc[ri][1] = pack2(fb.y, 0.0f);
            facc[ri][2] = pack2(fb.z, 0.0f);
            facc[ri][3] = pack2(fb.w, 0.0f);
        }
#pragma unroll 1
        for (int kt = 0; kt < 4; ++kt) {
            const int pn = (pcur + 1 == NPANEL) ? 0 : pcur + 1;
            float4 pf[8];
#pragma unroll
            for (int i = 0; i < 8; ++i)
                pf[i] = __ldg(panel_src(pn, tx + i * 256));

            const float* arow = nxt + kt * KT;
#pragma unroll 8
            for (int kk2 = 0; kk2 < KT / 2; ++kk2) {
                const ulonglong2 B0 = *reinterpret_cast<const ulonglong2*>(
                    Wp + kk2 * 256 + tj * 8);
                const ulonglong2 B1 = *reinterpret_cast<const ulonglong2*>(
                    Wp + kk2 * 256 + tj * 8 + 4);
#pragma unroll
                for (int ri = 0; ri < 8; ++ri) {
                    const unsigned long long a2 =
                        *reinterpret_cast<const unsigned long long*>(
                            arow + (rowbase + ri) * PADK + kk2 * 2);
                    fma2(facc[ri][0], a2, B0.x);
                    fma2(facc[ri][1], a2, B0.y);
                    fma2(facc[ri][2], a2, B1.x);
                    fma2(facc[ri][3], a2, B1.y);
                }
            }
            __syncthreads();
#pragma unroll
            for (int i = 0; i < 8; ++i)
                reinterpret_cast<float4*>(Wp)[tx + i * 256] = pf[i];
            __syncthreads();
            pcur = pn;
        }

#pragma unroll
        for (int ri = 0; ri < 8; ++ri) {
            const int n = r0 + rowbase + ri;
            float4 v;
            v.x = fold2(facc[ri][0]);
            v.y = fold2(facc[ri][1]);
            v.z = fold2(facc[ri][2]);
            v.w = fold2(facc[ri][3]);
            *reinterpret_cast<float4*>(
                out + (size_t)n * (LSTEPS * OUTD) + l * OUTD + tj * 4) = v;
        }
    }
}

extern "C" void kernel_launch(void* const* d_in, const int* in_sizes, int n_in,
                              void* d_out, int out_size) {
    const float* x    = (const float*)d_in[0];
    const float* W_ih = (const float*)d_in[1];
    const float* W_hh = (const float*)d_in[2];
    const float* b_ih = (const float*)d_in[3];
    const float* b_hh = (const float*)d_in[4];
    const float* fc_w = (const float*)d_in[5];
    const float* fc_b = (const float*)d_in[6];
    float* out = (float*)d_out;

    prep_kernel<<<128, 256>>>(W_ih, W_hh, b_ih, b_hh, fc_w);

    const size_t smem_bytes = (size_t)SMEM_FLOATS * sizeof(float);  // 230,400 B
    cudaFuncSetAttribute(lstm_kernel, cudaFuncAttributeMaxDynamicSharedMemorySize,
                         (int)smem_bytes);
    lstm_kernel<<<NCTA, 256, smem_bytes>>>(x, fc_b, out);
}